// round 7
// baseline (speedup 1.0000x reference)
#include <cuda_runtime.h>
#include <cuda_bf16.h>
#include <math.h>

#define N_NODES 100000
#define N_EDGES 1600000
#define E_TOT   (N_EDGES + N_NODES)
#define NEG_SLOPE 0.2f

// ---------------- scratch (static device globals; 16B-aligned for vector ops)
__device__ __align__(16) float g_xw1[N_NODES * 128];
__device__ __align__(16) float g_h[N_NODES * 128];     // layer-1 output accumulator
__device__ __align__(16) float g_al1[N_NODES * 4];
__device__ __align__(16) float g_ar1[N_NODES * 4];
__device__ __align__(16) float g_max1[N_NODES * 4];
__device__ __align__(16) float g_den1[N_NODES * 4];
__device__ __align__(16) float g_e1[E_TOT * 4];        // per-edge logits -> exp weights
__device__ __align__(16) int   g_src[E_TOT];
__device__ __align__(16) int   g_dst[E_TOT];

__device__ __align__(16) float g_xw2[N_NODES * 16];
__device__ __align__(16) float g_al2[N_NODES];
__device__ __align__(16) float g_ar2[N_NODES];
__device__ __align__(16) float g_max2[N_NODES];
__device__ __align__(16) float g_den2[N_NODES];
__device__ __align__(16) float g_e2[E_TOT];

// ---------------- small helpers --------------------------------------------
__device__ __forceinline__ float lrelu(float v) {
    return v > 0.f ? v : NEG_SLOPE * v;
}

// float atomic max via int/uint ordering trick (works across sign mix)
__device__ __forceinline__ void atomicMaxF(float* addr, float val) {
    if (val >= 0.f) atomicMax((int*)addr, __float_as_int(val));
    else            atomicMin((unsigned int*)addr, __float_as_uint(val));
}

// vectorized fire-and-forget atomic add (sm_90+: red.global.add.v4.f32)
// addr MUST be 16B aligned.
__device__ __forceinline__ void red_add_v4(float* addr, float a, float b, float c, float d) {
    asm volatile("red.global.add.v4.f32 [%0], {%1, %2, %3, %4};"
                 :: "l"(addr), "f"(a), "f"(b), "f"(c), "f"(d) : "memory");
}

// ---------------- init / prep ----------------------------------------------
__global__ void zero_kernel(float* p, int n) {
    for (int i = blockIdx.x * blockDim.x + threadIdx.x; i < n; i += gridDim.x * blockDim.x)
        p[i] = 0.f;
}
__global__ void fill_neginf_kernel(float* p, int n) {
    for (int i = blockIdx.x * blockDim.x + threadIdx.x; i < n; i += gridDim.x * blockDim.x)
        p[i] = -INFINITY;
}
// edge_index is INT32: JAX's default config disables x64, so the reference's
// "int64" randint array is materialized as int32. Layout: [2, E] row-major.
__global__ void prep_edges_kernel(const int* __restrict__ ei) {
    for (int i = blockIdx.x * blockDim.x + threadIdx.x; i < E_TOT; i += gridDim.x * blockDim.x) {
        if (i < N_EDGES) {
            g_src[i] = ei[i];
            g_dst[i] = ei[N_EDGES + i];
        } else {
            int n = i - N_EDGES;  // self loop
            g_src[i] = n;
            g_dst[i] = n;
        }
    }
}

// ---------------- layer 1: GEMM (x @ W1) + attention dots -------------------
// 8 nodes per 128-thread block. Thread t owns output column t for all 8 nodes.
#define G1_NODES 8
__global__ void gemm1_kernel(const float* __restrict__ x,
                             const float* __restrict__ W1,
                             const float* __restrict__ asrc,
                             const float* __restrict__ adst) {
    __shared__ __align__(16) float xs[G1_NODES * 128];
    int t = threadIdx.x;                 // 0..127 output column
    int nbase = blockIdx.x * G1_NODES;

    // load 8 x-rows into shared
    #pragma unroll
    for (int n = 0; n < G1_NODES; n++) {
        int node = nbase + n;
        xs[n * 128 + t] = (node < N_NODES) ? x[node * 128 + t] : 0.f;
    }
    __syncthreads();

    float acc[G1_NODES];
    #pragma unroll
    for (int n = 0; n < G1_NODES; n++) acc[n] = 0.f;

    const float4* xs4 = (const float4*)xs;
    #pragma unroll 4
    for (int kg = 0; kg < 32; kg++) {       // groups of 4 k
        int k = kg * 4;
        float w0 = W1[(k + 0) * 128 + t];
        float w1 = W1[(k + 1) * 128 + t];
        float w2 = W1[(k + 2) * 128 + t];
        float w3 = W1[(k + 3) * 128 + t];
        #pragma unroll
        for (int n = 0; n < G1_NODES; n++) {
            float4 xv = xs4[n * 32 + kg];
            acc[n] = fmaf(xv.x, w0, acc[n]);
            acc[n] = fmaf(xv.y, w1, acc[n]);
            acc[n] = fmaf(xv.z, w2, acc[n]);
            acc[n] = fmaf(xv.w, w3, acc[n]);
        }
    }

    int lane = t & 31, head = t >> 5;       // head == warp id (32 cols / head)
    float as = asrc[t];                     // a_src1[head][lane], flat 128
    float ad = adst[t];
    #pragma unroll
    for (int n = 0; n < G1_NODES; n++) {
        int node = nbase + n;
        if (node >= N_NODES) break;
        g_xw1[node * 128 + t] = acc[n];
        float al = acc[n] * as;
        float ar = acc[n] * ad;
        #pragma unroll
        for (int o = 16; o > 0; o >>= 1) {
            al += __shfl_down_sync(0xffffffffu, al, o);
            ar += __shfl_down_sync(0xffffffffu, ar, o);
        }
        if (lane == 0) {
            g_al1[node * 4 + head] = al;
            g_ar1[node * 4 + head] = ar;
        }
    }
}

// ---------------- layer 1 edge passes ---------------------------------------
__global__ void edge_b1_kernel() {
    for (int e = blockIdx.x * blockDim.x + threadIdx.x; e < E_TOT; e += gridDim.x * blockDim.x) {
        int s = g_src[e], d = g_dst[e];
        float4 al = *(const float4*)&g_al1[s * 4];
        float4 ar = *(const float4*)&g_ar1[d * 4];
        float4 ev;
        ev.x = lrelu(al.x + ar.x);
        ev.y = lrelu(al.y + ar.y);
        ev.z = lrelu(al.z + ar.z);
        ev.w = lrelu(al.w + ar.w);
        *(float4*)&g_e1[e * 4] = ev;
        atomicMaxF(&g_max1[d * 4 + 0], ev.x);
        atomicMaxF(&g_max1[d * 4 + 1], ev.y);
        atomicMaxF(&g_max1[d * 4 + 2], ev.z);
        atomicMaxF(&g_max1[d * 4 + 3], ev.w);
    }
}

__global__ void edge_c1_kernel() {
    for (int e = blockIdx.x * blockDim.x + threadIdx.x; e < E_TOT; e += gridDim.x * blockDim.x) {
        int d = g_dst[e];
        float4 ev = *(const float4*)&g_e1[e * 4];
        float4 mx = *(const float4*)&g_max1[d * 4];
        ev.x = __expf(ev.x - mx.x);
        ev.y = __expf(ev.y - mx.y);
        ev.z = __expf(ev.z - mx.z);
        ev.w = __expf(ev.w - mx.w);
        *(float4*)&g_e1[e * 4] = ev;
        red_add_v4(&g_den1[d * 4], ev.x, ev.y, ev.z, ev.w);
    }
}

// warp per edge: 32 lanes x float4 = 128 features
__global__ void edge_d1_kernel() {
    int gw = (blockIdx.x * blockDim.x + threadIdx.x) >> 5;
    int lane = threadIdx.x & 31;
    if (gw >= E_TOT) return;
    int s = g_src[gw], d = g_dst[gw];
    int head = lane >> 3;                  // 8 lanes (32 cols) per head
    float em  = g_e1[gw * 4 + head];
    float den = g_den1[d * 4 + head];
    float alpha = em / den;
    float4 v = *(const float4*)&g_xw1[s * 128 + lane * 4];
    red_add_v4(&g_h[d * 128 + lane * 4],
               v.x * alpha, v.y * alpha, v.z * alpha, v.w * alpha);
}

__global__ void bias_relu1_kernel(const float* __restrict__ b1) {
    for (int i = blockIdx.x * blockDim.x + threadIdx.x; i < N_NODES * 128;
         i += gridDim.x * blockDim.x) {
        float v = g_h[i] + b1[i & 127];
        g_h[i] = v > 0.f ? v : 0.f;
    }
}

// ---------------- layer 2: GEMM (h @ W2) + attention dots -------------------
// one warp per node; lanes 0..15 own a column, halves split k.
__global__ void gemm2_kernel(const float* __restrict__ W2,
                             const float* __restrict__ asrc,
                             const float* __restrict__ adst) {
    int warp = (blockIdx.x * blockDim.x + threadIdx.x) >> 5;
    int lane = threadIdx.x & 31;
    if (warp >= N_NODES) return;
    int col  = lane & 15;
    int half = lane >> 4;                 // 0 or 1 (k split 64/64)
    const float* hrow = &g_h[warp * 128 + half * 64];
    const float* wptr = &W2[half * 64 * 16 + col];
    float sum = 0.f;
    #pragma unroll 8
    for (int k = 0; k < 64; k++)
        sum = fmaf(hrow[k], wptr[k * 16], sum);
    sum += __shfl_xor_sync(0xffffffffu, sum, 16);
    float al = 0.f, ar = 0.f;
    if (lane < 16) {
        g_xw2[warp * 16 + col] = sum;
        al = sum * asrc[col];
        ar = sum * adst[col];
    }
    #pragma unroll
    for (int o = 8; o > 0; o >>= 1) {
        al += __shfl_down_sync(0xffffffffu, al, o);
        ar += __shfl_down_sync(0xffffffffu, ar, o);
    }
    if (lane == 0) { g_al2[warp] = al; g_ar2[warp] = ar; }
}

// ---------------- layer 2 edge passes ---------------------------------------
__global__ void edge_b2_kernel() {
    for (int e = blockIdx.x * blockDim.x + threadIdx.x; e < E_TOT; e += gridDim.x * blockDim.x) {
        int s = g_src[e], d = g_dst[e];
        float ev = lrelu(g_al2[s] + g_ar2[d]);
        g_e2[e] = ev;
        atomicMaxF(&g_max2[d], ev);
    }
}

__global__ void edge_c2_kernel() {
    for (int e = blockIdx.x * blockDim.x + threadIdx.x; e < E_TOT; e += gridDim.x * blockDim.x) {
        int d = g_dst[e];
        float em = __expf(g_e2[e] - g_max2[d]);
        g_e2[e] = em;
        atomicAdd(&g_den2[d], em);
    }
}

__global__ void edge_d2_kernel(float* __restrict__ out) {
    for (int e = blockIdx.x * blockDim.x + threadIdx.x; e < E_TOT; e += gridDim.x * blockDim.x) {
        int s = g_src[e], d = g_dst[e];
        float alpha = g_e2[e] / g_den2[d];
        const float4* xv = (const float4*)&g_xw2[s * 16];
        float* ov = &out[d * 16];
        #pragma unroll
        for (int j = 0; j < 4; j++) {
            float4 v = xv[j];
            red_add_v4(ov + j * 4, v.x * alpha, v.y * alpha, v.z * alpha, v.w * alpha);
        }
    }
}

__global__ void bias2_kernel(float* __restrict__ out, const float* __restrict__ b2) {
    for (int i = blockIdx.x * blockDim.x + threadIdx.x; i < N_NODES * 16;
         i += gridDim.x * blockDim.x) {
        out[i] += b2[i & 15];
    }
}

// ---------------- launch ----------------------------------------------------
extern "C" void kernel_launch(void* const* d_in, const int* in_sizes, int n_in,
                              void* d_out, int out_size) {
    const float* x     = (const float*)d_in[0];
    const int*   ei    = (const int*)d_in[1];      // int32! (JAX x64 disabled)
    const float* W1    = (const float*)d_in[2];
    const float* asrc1 = (const float*)d_in[3];
    const float* adst1 = (const float*)d_in[4];
    const float* b1    = (const float*)d_in[5];
    const float* W2    = (const float*)d_in[6];
    const float* asrc2 = (const float*)d_in[7];
    const float* adst2 = (const float*)d_in[8];
    const float* b2    = (const float*)d_in[9];
    float* out = (float*)d_out;

    static float *p_h = nullptr, *p_den1, *p_max1, *p_den2, *p_max2;
    if (!p_h) {
        cudaGetSymbolAddress((void**)&p_h,    g_h);
        cudaGetSymbolAddress((void**)&p_den1, g_den1);
        cudaGetSymbolAddress((void**)&p_max1, g_max1);
        cudaGetSymbolAddress((void**)&p_den2, g_den2);
        cudaGetSymbolAddress((void**)&p_max2, g_max2);
    }

    const int TB = 256;

    // init
    zero_kernel<<<2048, TB>>>(p_h, N_NODES * 128);
    zero_kernel<<<512,  TB>>>(out, N_NODES * 16);
    zero_kernel<<<256,  TB>>>(p_den1, N_NODES * 4);
    zero_kernel<<<128,  TB>>>(p_den2, N_NODES);
    fill_neginf_kernel<<<256, TB>>>(p_max1, N_NODES * 4);
    fill_neginf_kernel<<<128, TB>>>(p_max2, N_NODES);
    prep_edges_kernel<<<2048, TB>>>(ei);

    // layer 1
    gemm1_kernel<<<(N_NODES + G1_NODES - 1) / G1_NODES, 128>>>(x, W1, asrc1, adst1);
    edge_b1_kernel<<<(E_TOT + TB - 1) / TB, TB>>>();
    edge_c1_kernel<<<(E_TOT + TB - 1) / TB, TB>>>();
    {
        long long threads = (long long)E_TOT * 32;
        int blocks = (int)((threads + TB - 1) / TB);
        edge_d1_kernel<<<blocks, TB>>>();
    }
    bias_relu1_kernel<<<4096, TB>>>(b1);

    // layer 2
    {
        long long threads = (long long)N_NODES * 32;
        int blocks = (int)((threads + TB - 1) / TB);
        gemm2_kernel<<<blocks, TB>>>(W2, asrc2, adst2);
    }
    edge_b2_kernel<<<(E_TOT + TB - 1) / TB, TB>>>();
    edge_c2_kernel<<<(E_TOT + TB - 1) / TB, TB>>>();
    edge_d2_kernel<<<(E_TOT + TB - 1) / TB, TB>>>(out);
    bias2_kernel<<<1024, TB>>>(out, b2);
}

// round 10
// speedup vs baseline: 1.7578x; 1.7578x over previous
#include <cuda_runtime.h>
#include <cuda_bf16.h>
#include <math.h>

#define N_NODES 100000
#define N_EDGES 1600000
#define E_TOT   (N_EDGES + N_NODES)
#define NEG_SLOPE 0.2f

// ---------------- scratch (static device globals) ---------------------------
__device__ __align__(16) float g_xw1[N_NODES * 128];
__device__ __align__(16) float g_al1[N_NODES * 4];
__device__ __align__(16) float g_ar1[N_NODES * 4];
__device__ __align__(16) float g_xw2[N_NODES * 16];
__device__ __align__(16) float g_al2[N_NODES];
__device__ __align__(16) float g_ar2[N_NODES];
__device__ int g_deg[N_NODES];     // in-degree (incl. self loop)
__device__ int g_row[N_NODES];     // CSR row start
__device__ int g_fill[N_NODES];    // scatter cursor
__device__ int g_csr_src[E_TOT];   // src node id per CSR slot
__device__ int g_cursor;           // global allocation cursor for scan

// ---------------- helpers ---------------------------------------------------
__device__ __forceinline__ float lrelu(float v) {
    return v > 0.f ? v : NEG_SLOPE * v;
}

// ---------------- CSR build --------------------------------------------------
__global__ void hist_kernel(const int* __restrict__ ei) {
    for (int i = blockIdx.x * blockDim.x + threadIdx.x; i < E_TOT; i += gridDim.x * blockDim.x) {
        int d = (i < N_EDGES) ? ei[N_EDGES + i] : (i - N_EDGES);
        atomicAdd(&g_deg[d], 1);
    }
}

#define SCAN_B 256
__global__ void scan_kernel() {
    __shared__ int sdata[SCAN_B];
    __shared__ int base;
    int t = threadIdx.x;
    int d = blockIdx.x * SCAN_B + t;
    int deg = (d < N_NODES) ? g_deg[d] : 0;
    sdata[t] = deg;
    __syncthreads();
    #pragma unroll
    for (int off = 1; off < SCAN_B; off <<= 1) {
        int v = 0;
        if (t >= off) v = sdata[t - off];
        __syncthreads();
        if (t >= off) sdata[t] += v;
        __syncthreads();
    }
    int incl = sdata[t];
    int excl = incl - deg;
    if (t == SCAN_B - 1) base = atomicAdd(&g_cursor, incl);
    __syncthreads();
    if (d < N_NODES) {
        int r = base + excl;
        g_row[d]  = r;
        g_fill[d] = r;
    }
}

__global__ void scatter_kernel(const int* __restrict__ ei) {
    for (int i = blockIdx.x * blockDim.x + threadIdx.x; i < E_TOT; i += gridDim.x * blockDim.x) {
        int s, d;
        if (i < N_EDGES) { s = ei[i]; d = ei[N_EDGES + i]; }
        else             { s = d = i - N_EDGES; }
        int pos = atomicAdd(&g_fill[d], 1);
        g_csr_src[pos] = s;
    }
}

// ---------------- layer 1 GEMM: x @ W1 + attention dots ---------------------
#define G1_NODES 8
__global__ void gemm1_kernel(const float* __restrict__ x,
                             const float* __restrict__ W1,
                             const float* __restrict__ asrc,
                             const float* __restrict__ adst) {
    __shared__ __align__(16) float xs[G1_NODES * 128];
    int t = threadIdx.x;
    int nbase = blockIdx.x * G1_NODES;

    #pragma unroll
    for (int n = 0; n < G1_NODES; n++) {
        int node = nbase + n;
        xs[n * 128 + t] = (node < N_NODES) ? x[node * 128 + t] : 0.f;
    }
    __syncthreads();

    float acc[G1_NODES];
    #pragma unroll
    for (int n = 0; n < G1_NODES; n++) acc[n] = 0.f;

    const float4* xs4 = (const float4*)xs;
    #pragma unroll 4
    for (int kg = 0; kg < 32; kg++) {
        int k = kg * 4;
        float w0 = W1[(k + 0) * 128 + t];
        float w1 = W1[(k + 1) * 128 + t];
        float w2 = W1[(k + 2) * 128 + t];
        float w3 = W1[(k + 3) * 128 + t];
        #pragma unroll
        for (int n = 0; n < G1_NODES; n++) {
            float4 xv = xs4[n * 32 + kg];
            acc[n] = fmaf(xv.x, w0, acc[n]);
            acc[n] = fmaf(xv.y, w1, acc[n]);
            acc[n] = fmaf(xv.z, w2, acc[n]);
            acc[n] = fmaf(xv.w, w3, acc[n]);
        }
    }

    int lane = t & 31, head = t >> 5;
    float as = asrc[t];
    float ad = adst[t];
    #pragma unroll
    for (int n = 0; n < G1_NODES; n++) {
        int node = nbase + n;
        if (node >= N_NODES) break;
        g_xw1[node * 128 + t] = acc[n];
        float al = acc[n] * as;
        float ar = acc[n] * ad;
        #pragma unroll
        for (int o = 16; o > 0; o >>= 1) {
            al += __shfl_down_sync(0xffffffffu, al, o);
            ar += __shfl_down_sync(0xffffffffu, ar, o);
        }
        if (lane == 0) {
            g_al1[node * 4 + head] = al;
            g_ar1[node * 4 + head] = ar;
        }
    }
}

// ---------------- fused layer-1 aggregation + layer-2 GEMM ------------------
// One warp per dst node. No atomics: per-node softmax denom and weighted sum
// held in registers. Epilogue: bias+ReLU, h@W2, al2/ar2.
#define F1_WARPS 8
__global__ void fused1_kernel(const float* __restrict__ b1,
                              const float* __restrict__ W2,
                              const float* __restrict__ asrc2,
                              const float* __restrict__ adst2) {
    __shared__ __align__(16) float W2t[16 * 128];   // transposed: [c][k]
    int t = threadIdx.x;
    #pragma unroll
    for (int i = t; i < 16 * 128; i += F1_WARPS * 32) {
        int c = i >> 7, k = i & 127;
        W2t[i] = W2[k * 16 + c];
    }
    __syncthreads();

    int warp = t >> 5, lane = t & 31;
    int d = blockIdx.x * F1_WARPS + warp;
    if (d >= N_NODES) return;

    int row = g_row[d];
    int deg = g_deg[d];
    float4 ar4 = *(const float4*)&g_ar1[d * 4];

    // ---- pass 1: per-head softmax denominators (no max; mathematically exact)
    float den0 = 0.f, den1 = 0.f, den2 = 0.f, den3 = 0.f;
    for (int i = lane; i < deg; i += 32) {
        int s = g_csr_src[row + i];
        float4 al = *(const float4*)&g_al1[s * 4];
        den0 += __expf(lrelu(al.x + ar4.x));
        den1 += __expf(lrelu(al.y + ar4.y));
        den2 += __expf(lrelu(al.z + ar4.z));
        den3 += __expf(lrelu(al.w + ar4.w));
    }
    #pragma unroll
    for (int o = 16; o > 0; o >>= 1) {
        den0 += __shfl_xor_sync(0xffffffffu, den0, o);
        den1 += __shfl_xor_sync(0xffffffffu, den1, o);
        den2 += __shfl_xor_sync(0xffffffffu, den2, o);
        den3 += __shfl_xor_sync(0xffffffffu, den3, o);
    }

    int head = lane >> 3;                     // xw1 row layout: head*32 + c
    float ar_h  = (head < 2) ? (head == 0 ? ar4.x : ar4.y)
                             : (head == 2 ? ar4.z : ar4.w);
    float inv_h = (head < 2) ? (head == 0 ? den0 : den1)
                             : (head == 2 ? den2 : den3);
    inv_h = 1.f / inv_h;

    // ---- pass 2: warp-collective weighted gather of xw1 rows
    float4 acc = make_float4(0.f, 0.f, 0.f, 0.f);
    for (int i = 0; i < deg; i++) {
        int s = g_csr_src[row + i];           // uniform across warp
        float alh = g_al1[s * 4 + head];
        float alpha = __expf(lrelu(alh + ar_h)) * inv_h;
        float4 v = *(const float4*)&g_xw1[s * 128 + lane * 4];
        acc.x = fmaf(v.x, alpha, acc.x);
        acc.y = fmaf(v.y, alpha, acc.y);
        acc.z = fmaf(v.z, alpha, acc.z);
        acc.w = fmaf(v.w, alpha, acc.w);
    }

    // ---- epilogue: bias + ReLU -> h row (in registers, 4 per lane)
    float4 bb = *(const float4*)&b1[lane * 4];
    acc.x = fmaxf(acc.x + bb.x, 0.f);
    acc.y = fmaxf(acc.y + bb.y, 0.f);
    acc.z = fmaxf(acc.z + bb.z, 0.f);
    acc.w = fmaxf(acc.w + bb.w, 0.f);

    // ---- h @ W2 (128x16) without touching global h
    float p[16];
    #pragma unroll
    for (int c = 0; c < 16; c++) {
        const float4 w = *(const float4*)&W2t[c * 128 + lane * 4];
        p[c] = acc.x * w.x + acc.y * w.y + acc.z * w.z + acc.w * w.w;
    }
    #pragma unroll
    for (int c = 0; c < 16; c++) {
        #pragma unroll
        for (int o = 16; o > 0; o >>= 1)
            p[c] += __shfl_down_sync(0xffffffffu, p[c], o);
    }
    if (lane == 0) {
        float al2 = 0.f, ar2 = 0.f;
        #pragma unroll
        for (int c = 0; c < 16; c++) {
            al2 = fmaf(p[c], asrc2[c], al2);
            ar2 = fmaf(p[c], adst2[c], ar2);
        }
        float4* o4 = (float4*)&g_xw2[d * 16];
        o4[0] = make_float4(p[0],  p[1],  p[2],  p[3]);
        o4[1] = make_float4(p[4],  p[5],  p[6],  p[7]);
        o4[2] = make_float4(p[8],  p[9],  p[10], p[11]);
        o4[3] = make_float4(p[12], p[13], p[14], p[15]);
        g_al2[d] = al2;
        g_ar2[d] = ar2;
    }
}

// ---------------- fused layer-2 aggregation + bias --------------------------
// One warp per dst node; half-warps process alternate edges (16 features each).
#define F2_WARPS 8
__global__ void fused2_kernel(const float* __restrict__ b2,
                              float* __restrict__ out) {
    int t = threadIdx.x;
    int warp = t >> 5, lane = t & 31;
    int d = blockIdx.x * F2_WARPS + warp;
    if (d >= N_NODES) return;

    int row = g_row[d];
    int deg = g_deg[d];
    float ard = g_ar2[d];

    float den = 0.f;
    for (int i = lane; i < deg; i += 32) {
        int s = g_csr_src[row + i];
        den += __expf(lrelu(g_al2[s] + ard));
    }
    #pragma unroll
    for (int o = 16; o > 0; o >>= 1)
        den += __shfl_xor_sync(0xffffffffu, den, o);
    float inv = 1.f / den;

    int half = lane >> 4, l16 = lane & 15;
    float acc = 0.f;
    for (int i = half; i < deg; i += 2) {
        int s = g_csr_src[row + i];           // uniform per half-warp
        float alpha = __expf(lrelu(g_al2[s] + ard)) * inv;
        acc = fmaf(g_xw2[s * 16 + l16], alpha, acc);
    }
    acc += __shfl_xor_sync(0xffffffffu, acc, 16);
    if (lane < 16) out[d * 16 + lane] = acc + b2[lane];
}

// ---------------- launch ----------------------------------------------------
extern "C" void kernel_launch(void* const* d_in, const int* in_sizes, int n_in,
                              void* d_out, int out_size) {
    const float* x     = (const float*)d_in[0];
    const int*   ei    = (const int*)d_in[1];      // int32 (JAX x64 disabled)
    const float* W1    = (const float*)d_in[2];
    const float* asrc1 = (const float*)d_in[3];
    const float* adst1 = (const float*)d_in[4];
    const float* b1    = (const float*)d_in[5];
    const float* W2    = (const float*)d_in[6];
    const float* asrc2 = (const float*)d_in[7];
    const float* adst2 = (const float*)d_in[8];
    const float* b2    = (const float*)d_in[9];
    float* out = (float*)d_out;

    static void *p_deg = nullptr, *p_cursor = nullptr;
    if (!p_deg) {
        cudaGetSymbolAddress(&p_deg,    g_deg);
        cudaGetSymbolAddress(&p_cursor, g_cursor);
    }

    const int TB = 256;

    // CSR build
    cudaMemsetAsync(p_deg, 0, N_NODES * sizeof(int));
    cudaMemsetAsync(p_cursor, 0, sizeof(int));
    hist_kernel<<<2048, TB>>>(ei);
    scan_kernel<<<(N_NODES + SCAN_B - 1) / SCAN_B, SCAN_B>>>();
    scatter_kernel<<<2048, TB>>>(ei);

    // layer 1 GEMM + attention dots
    gemm1_kernel<<<(N_NODES + G1_NODES - 1) / G1_NODES, 128>>>(x, W1, asrc1, adst1);

    // fused layer-1 aggregation + layer-2 projection
    fused1_kernel<<<(N_NODES + F1_WARPS - 1) / F1_WARPS, F1_WARPS * 32>>>(b1, W2, asrc2, adst2);

    // fused layer-2 aggregation + bias
    fused2_kernel<<<(N_NODES + F2_WARPS - 1) / F2_WARPS, F2_WARPS * 32>>>(b2, out);
}